// round 2
// baseline (speedup 1.0000x reference)
#include <cuda_runtime.h>
#include <cstdint>

// Problem constants
#define QN 8192
#define SN 30
#define DN 512

constexpr int THREADS = 128;
constexpr int ROWS_PER_BLOCK = 8;   // 2 rows per warp (16-lane groups), 4 warps
constexpr int SC = 10;              // support chunk per pass
constexpr int NPASS = 3;            // 3 * 10 = 30 supports

typedef unsigned long long ull;

// Packed f32x2 helpers (sm_100+): double fp32 vector throughput vs scalar FFMA.
__device__ __forceinline__ ull psub(ull a, ull b) {
    ull r; asm("sub.rn.f32x2 %0, %1, %2;" : "=l"(r) : "l"(a), "l"(b)); return r;
}
__device__ __forceinline__ ull pfma(ull a, ull b, ull c) {
    ull r; asm("fma.rn.f32x2 %0, %1, %2, %3;" : "=l"(r) : "l"(a), "l"(b), "l"(c)); return r;
}
__device__ __forceinline__ float plo(ull a) { return __uint_as_float((unsigned)(a & 0xffffffffu)); }
__device__ __forceinline__ float phi(ull a) { return __uint_as_float((unsigned)(a >> 32)); }

#define ABS2 0x7fffffff7fffffffULL

__global__ __launch_bounds__(THREADS)
void resus_kernel(const float* __restrict__ qenc,   // [Q, D]
                  const float* __restrict__ senc,   // [S, D]
                  const float* __restrict__ sy,     // [1, S]
                  const float* __restrict__ sp,     // [S]
                  const float* __restrict__ qp,     // [Q]
                  const float* __restrict__ w,      // [D]
                  const float* __restrict__ ascale, // [THRESH,1]
                  const float* __restrict__ abias,  // [THRESH,1]
                  const int*   __restrict__ nsamp,  // scalar
                  float* __restrict__ out)          // [2*Q]: pred then mean_l2
{
    __shared__ float scoreSh[ROWS_PER_BLOCK][SN + 2];
    __shared__ float l2Sh[ROWS_PER_BLOCK];
    __shared__ float dySh[SN];
    __shared__ float sb[2]; // scale, bias

    const int tid = threadIdx.x;

    if (tid < SN) {
        float p = sp[tid];
        dySh[tid] = sy[tid] - 1.0f / (1.0f + expf(-p));
    }
    if (tid == 0) {
        int idx = nsamp[0] - 1;
        sb[0] = fabsf(ascale[idx]);
        sb[1] = abias[idx];
    }

    const int lane = tid & 31;
    const int warp = tid >> 5;
    const int g = lane >> 4;   // row group within warp (0..1)
    const int j = lane & 15;   // d-slice lane within group (0..15)

    const int rowLocal = warp * 2 + g;            // 0..7
    const int row = blockIdx.x * ROWS_PER_BLOCK + rowLocal;

    const float* qr = qenc + (size_t)row * DN;

    float l2run = 0.0f;

#pragma unroll 1
    for (int pass = 0; pass < NPASS; pass++) {
        const int s0 = pass * SC;
        const float* sbase = senc + (size_t)s0 * DN;

        ull aS[SC], aL[SC];
#pragma unroll
        for (int s = 0; s < SC; s++) { aS[s] = aL[s] = 0ull; }

#pragma unroll 1
        for (int i = 0; i < 8; i++) {
            const int d0 = 4 * j + 64 * i;
            // Coalesced LDG.128s: the 16 lanes of a group cover 256 consecutive bytes.
            ulonglong2 qv = *reinterpret_cast<const ulonglong2*>(qr + d0);
            ulonglong2 wv = *reinterpret_cast<const ulonglong2*>(w + d0);
#pragma unroll
            for (int s = 0; s < SC; s++) {
                ulonglong2 sv = *reinterpret_cast<const ulonglong2*>(sbase + (size_t)s * DN + d0);
                ull dlo = psub(qv.x, sv.x);
                ull dhi = psub(qv.y, sv.y);
                aL[s] = pfma(dlo, dlo, aL[s]);
                aL[s] = pfma(dhi, dhi, aL[s]);
                aS[s] = pfma(dlo & ABS2, wv.x, aS[s]);
                aS[s] = pfma(dhi & ABS2, wv.y, aS[s]);
            }
        }

        // Reduce packed halves, then across the 16 lanes of the group.
#pragma unroll
        for (int s = 0; s < SC; s++) {
            float vS = plo(aS[s]) + phi(aS[s]);
            float vL = plo(aL[s]) + phi(aL[s]);
#pragma unroll
            for (int m = 1; m < 16; m <<= 1) {
                vS += __shfl_xor_sync(0xffffffffu, vS, m);
                vL += __shfl_xor_sync(0xffffffffu, vL, m);
            }
            if (j == 0) scoreSh[rowLocal][s0 + s] = vS;
            l2run += __fsqrt_rn(vL);
        }
    }

    if (j == 0) l2Sh[rowLocal] = l2run;
    __syncthreads();

    // Epilogue: one thread per row. Softmax over S, dot with delta_y, adjust.
    if (tid < ROWS_PER_BLOCK) {
        const int row2 = blockIdx.x * ROWS_PER_BLOCK + tid;
        float mx = -1e30f;
#pragma unroll
        for (int s = 0; s < SN; s++) mx = fmaxf(mx, scoreSh[tid][s]);
        float den = 0.0f, num = 0.0f;
#pragma unroll
        for (int s = 0; s < SN; s++) {
            float e = expf(scoreSh[tid][s] - mx);
            den += e;
            num += e * dySh[s];
        }
        float dyh = num / den;
        out[row2]      = dyh * sb[0] + sb[1] + qp[row2];
        out[QN + row2] = l2Sh[tid] * (1.0f / (float)SN);
    }
}

extern "C" void kernel_launch(void* const* d_in, const int* in_sizes, int n_in,
                              void* d_out, int out_size) {
    const float* qenc   = (const float*)d_in[0]; // query_encode  [8192,512]
    const float* senc   = (const float*)d_in[1]; // support_encode [30,512]
    const float* sy     = (const float*)d_in[2]; // support_y [1,30]
    const float* sp     = (const float*)d_in[3]; // support_predict [30]
    const float* qp     = (const float*)d_in[4]; // query_predict [8192]
    const float* w      = (const float*)d_in[5]; // fc1_w [512]
    // d_in[6] = fc1_b: softmax-invariant, unused
    const float* ascale = (const float*)d_in[7]; // adjust_scale [30,1]
    const float* abias  = (const float*)d_in[8]; // adjust_bias [30,1]
    const int*   nsamp  = (const int*)d_in[9];   // num_samples

    float* out = (float*)d_out;

    dim3 grid(QN / ROWS_PER_BLOCK); // 1024
    dim3 block(THREADS);            // 128
    resus_kernel<<<grid, block>>>(qenc, senc, sy, sp, qp, w, ascale, abias, nsamp, out);
}

// round 3
// speedup vs baseline: 1.3590x; 1.3590x over previous
#include <cuda_runtime.h>
#include <cstdint>

#define QN 8192
#define SN 30
#define DN 512

constexpr int THREADS = 1024;   // 32 warps
constexpr int GRID    = 148;    // 1 block per SM
constexpr int STRIDE  = 516;    // shared row stride (floats): conflict-free LDS.128
constexpr int NPAIRS  = QN / 2; // 4096 row pairs

typedef unsigned long long ull;

__device__ __forceinline__ ull psub(ull a, ull b) {
    ull r; asm("sub.rn.f32x2 %0, %1, %2;" : "=l"(r) : "l"(a), "l"(b)); return r;
}
__device__ __forceinline__ ull pfma(ull a, ull b, ull c) {
    ull r; asm("fma.rn.f32x2 %0, %1, %2, %3;" : "=l"(r) : "l"(a), "l"(b), "l"(c)); return r;
}
__device__ __forceinline__ float plo(ull a) { return __uint_as_float((unsigned)(a & 0xffffffffu)); }
__device__ __forceinline__ float phi(ull a) { return __uint_as_float((unsigned)(a >> 32)); }

#define ABS2 0x7fffffff7fffffffULL

__global__ __launch_bounds__(THREADS, 1)
void resus_kernel(const float* __restrict__ qenc,   // [Q, D]
                  const float* __restrict__ senc,   // [S, D]
                  const float* __restrict__ sy,     // [1, S]
                  const float* __restrict__ sp,     // [S]
                  const float* __restrict__ qp,     // [Q]
                  const float* __restrict__ w,      // [D]
                  const float* __restrict__ ascale, // [THRESH,1]
                  const float* __restrict__ abias,  // [THRESH,1]
                  const int*   __restrict__ nsamp,  // scalar
                  float* __restrict__ out)          // [2*Q]
{
    extern __shared__ float sh[];
    float* sT  = sh;                 // [32][STRIDE] support rows (30 real + 2 zero)
    float* wSh = sh + 32 * STRIDE;   // [512]

    const int tid  = threadIdx.x;
    const int lane = tid & 31;
    const int warp = tid >> 5;

    // Stage support (rows 30,31 zeroed) and w into shared.
    for (int idx = tid; idx < 32 * DN; idx += THREADS) {
        int s = idx >> 9, d = idx & (DN - 1);
        sT[s * STRIDE + d] = (s < SN) ? senc[idx] : 0.0f;
    }
    for (int d = tid; d < DN; d += THREADS) wSh[d] = w[d];

    // Per-lane constants: delta_y for this lane's support, adjust params.
    float dyv = 0.0f;
    if (lane < SN) dyv = sy[lane] - 1.0f / (1.0f + __expf(-sp[lane]));
    const int ia = nsamp[0] - 1;
    const float scl = fabsf(ascale[ia]);
    const float bia = abias[ia];
    __syncthreads();

    const float* sRow = sT + lane * STRIDE;  // lane's private support row

    // Balanced per-SM row-pair ranges.
    const int pbeg = (NPAIRS * blockIdx.x) / GRID;
    const int pend = (NPAIRS * (blockIdx.x + 1)) / GRID;

    for (int p = pbeg + warp; p < pend; p += 32) {
        const int r0 = 2 * p;
        const float* q0 = qenc + (size_t)r0 * DN;
        const float* q1 = q0 + DN;

        ull aS0a = 0, aS0b = 0, aL0a = 0, aL0b = 0;
        ull aS1a = 0, aS1b = 0, aL1a = 0, aL1b = 0;

#pragma unroll 8
        for (int i = 0; i < DN / 4; i++) {
            ulonglong2 sv = *reinterpret_cast<const ulonglong2*>(sRow + 4 * i);
            ulonglong2 wv = *reinterpret_cast<const ulonglong2*>(wSh + 4 * i);
            ulonglong2 qa = *reinterpret_cast<const ulonglong2*>(q0 + 4 * i);
            ulonglong2 qb = *reinterpret_cast<const ulonglong2*>(q1 + 4 * i);

            ull d0 = psub(qa.x, sv.x);
            ull d1 = psub(qa.y, sv.y);
            aL0a = pfma(d0, d0, aL0a);
            aL0b = pfma(d1, d1, aL0b);
            aS0a = pfma(d0 & ABS2, wv.x, aS0a);
            aS0b = pfma(d1 & ABS2, wv.y, aS0b);

            ull e0 = psub(qb.x, sv.x);
            ull e1 = psub(qb.y, sv.y);
            aL1a = pfma(e0, e0, aL1a);
            aL1b = pfma(e1, e1, aL1b);
            aS1a = pfma(e0 & ABS2, wv.x, aS1a);
            aS1b = pfma(e1 & ABS2, wv.y, aS1b);
        }

        // Per-lane finalize: complete score/l2 for (row, s=lane).
        float sc0 = plo(aS0a) + phi(aS0a) + plo(aS0b) + phi(aS0b);
        float sc1 = plo(aS1a) + phi(aS1a) + plo(aS1b) + phi(aS1b);
        float l20 = __fsqrt_rn(plo(aL0a) + phi(aL0a) + plo(aL0b) + phi(aL0b));
        float l21 = __fsqrt_rn(plo(aL1a) + phi(aL1a) + plo(aL1b) + phi(aL1b));
        if (lane >= SN) { sc0 = -3.4e38f; sc1 = -3.4e38f; l20 = 0.0f; l21 = 0.0f; }

        // Warp softmax + weighted sums for both rows.
        float m0 = sc0, m1 = sc1;
#pragma unroll
        for (int d = 16; d; d >>= 1) {
            m0 = fmaxf(m0, __shfl_xor_sync(0xffffffffu, m0, d));
            m1 = fmaxf(m1, __shfl_xor_sync(0xffffffffu, m1, d));
        }
        float e0 = __expf(sc0 - m0);
        float e1 = __expf(sc1 - m1);
        float se0 = e0, sd0 = e0 * dyv, sl0 = l20;
        float se1 = e1, sd1 = e1 * dyv, sl1 = l21;
#pragma unroll
        for (int d = 16; d; d >>= 1) {
            se0 += __shfl_xor_sync(0xffffffffu, se0, d);
            sd0 += __shfl_xor_sync(0xffffffffu, sd0, d);
            sl0 += __shfl_xor_sync(0xffffffffu, sl0, d);
            se1 += __shfl_xor_sync(0xffffffffu, se1, d);
            sd1 += __shfl_xor_sync(0xffffffffu, sd1, d);
            sl1 += __shfl_xor_sync(0xffffffffu, sl1, d);
        }
        if (lane == 0) {
            out[r0]          = (sd0 / se0) * scl + bia + qp[r0];
            out[r0 + 1]      = (sd1 / se1) * scl + bia + qp[r0 + 1];
            out[QN + r0]     = sl0 * (1.0f / (float)SN);
            out[QN + r0 + 1] = sl1 * (1.0f / (float)SN);
        }
    }
}

extern "C" void kernel_launch(void* const* d_in, const int* in_sizes, int n_in,
                              void* d_out, int out_size) {
    const float* qenc   = (const float*)d_in[0];
    const float* senc   = (const float*)d_in[1];
    const float* sy     = (const float*)d_in[2];
    const float* sp     = (const float*)d_in[3];
    const float* qp     = (const float*)d_in[4];
    const float* w      = (const float*)d_in[5];
    // d_in[6] = fc1_b (softmax-invariant, unused)
    const float* ascale = (const float*)d_in[7];
    const float* abias  = (const float*)d_in[8];
    const int*   nsamp  = (const int*)d_in[9];

    float* out = (float*)d_out;

    const int smemBytes = (32 * STRIDE + DN) * (int)sizeof(float); // ~68 KB
    cudaFuncSetAttribute(resus_kernel,
                         cudaFuncAttributeMaxDynamicSharedMemorySize, smemBytes);

    resus_kernel<<<GRID, THREADS, smemBytes>>>(qenc, senc, sy, sp, qp, w,
                                               ascale, abias, nsamp, out);
}

// round 4
// speedup vs baseline: 1.5327x; 1.1278x over previous
#include <cuda_runtime.h>
#include <cstdint>

#define QN 8192
#define SN 30
#define DN 512

constexpr int THREADS = 512;    // 16 warps -> 128 regs/thread available
constexpr int GRID    = 148;    // 1 block per SM
constexpr int STRIDE  = 516;    // smem row stride: conflict-free lane-strided LDS.128
constexpr int NQUAD   = QN / 4; // 2048 row-quads

typedef unsigned long long ull;

__device__ __forceinline__ ull psub(ull a, ull b) {
    ull r; asm("sub.rn.f32x2 %0, %1, %2;" : "=l"(r) : "l"(a), "l"(b)); return r;
}
__device__ __forceinline__ ull pfma(ull a, ull b, ull c) {
    ull r; asm("fma.rn.f32x2 %0, %1, %2, %3;" : "=l"(r) : "l"(a), "l"(b), "l"(c)); return r;
}
__device__ __forceinline__ float plo(ull a) { return __uint_as_float((unsigned)(a & 0xffffffffu)); }
__device__ __forceinline__ float phi(ull a) { return __uint_as_float((unsigned)(a >> 32)); }
__device__ __forceinline__ void pf_l2(const float* p) {
    asm volatile("prefetch.global.L2 [%0];" :: "l"(p));
}

#define ABS2 0x7fffffff7fffffffULL

__global__ __launch_bounds__(THREADS, 1)
void resus_kernel(const float* __restrict__ qenc,
                  const float* __restrict__ senc,
                  const float* __restrict__ sy,
                  const float* __restrict__ sp,
                  const float* __restrict__ qp,
                  const float* __restrict__ w,
                  const float* __restrict__ ascale,
                  const float* __restrict__ abias,
                  const int*   __restrict__ nsamp,
                  float* __restrict__ out)
{
    extern __shared__ float sh[];
    float* sT  = sh;                 // [32][STRIDE] support rows (30 real + 2 zero)
    float* wSh = sh + 32 * STRIDE;   // [512]

    const int tid  = threadIdx.x;
    const int lane = tid & 31;
    const int warp = tid >> 5;

    for (int idx = tid; idx < 32 * DN; idx += THREADS) {
        int s = idx >> 9, d = idx & (DN - 1);
        sT[s * STRIDE + d] = (s < SN) ? senc[idx] : 0.0f;
    }
    for (int d = tid; d < DN; d += THREADS) wSh[d] = w[d];

    float dyv = 0.0f;
    if (lane < SN) dyv = sy[lane] - 1.0f / (1.0f + __expf(-sp[lane]));
    const int ia = nsamp[0] - 1;
    const float scl = fabsf(ascale[ia]);
    const float bia = abias[ia];
    __syncthreads();

    const int quad = warp * GRID + blockIdx.x;   // balanced: 13-14 quads per SM
    if (quad >= NQUAD) return;

    const float* sRow = sT + lane * STRIDE;
    const float* qbase = qenc + (size_t)quad * 4 * DN;

    ull aS[4], aL[4];
#pragma unroll
    for (int r = 0; r < 4; r++) { aS[r] = 0; aL[r] = 0; }

    // Double-buffered q chunks: 8 floats (4 ull) per row per chunk, 64 chunks.
    ull qA[16], qB[16];

#define LOADQ(BUF, C)                                                          \
    do {                                                                       \
        _Pragma("unroll")                                                      \
        for (int r = 0; r < 4; r++) {                                          \
            const float* p = qbase + r * DN + (C) * 8;                         \
            ulonglong2 t0 = *reinterpret_cast<const ulonglong2*>(p);           \
            ulonglong2 t1 = *reinterpret_cast<const ulonglong2*>(p + 4);       \
            BUF[r*4+0] = t0.x; BUF[r*4+1] = t0.y;                              \
            BUF[r*4+2] = t1.x; BUF[r*4+3] = t1.y;                              \
            pf_l2(p + 16);  /* L2 prefetch two chunks ahead */                 \
        }                                                                      \
    } while (0)

#define COMPUTE(BUF, C)                                                        \
    do {                                                                       \
        _Pragma("unroll")                                                      \
        for (int i = 0; i < 2; i++) {                                          \
            const int dd = (C) * 8 + i * 4;                                    \
            ulonglong2 sv = *reinterpret_cast<const ulonglong2*>(sRow + dd);   \
            ulonglong2 wv = *reinterpret_cast<const ulonglong2*>(wSh + dd);    \
            _Pragma("unroll")                                                  \
            for (int r = 0; r < 4; r++) {                                      \
                ull d0 = psub(BUF[r*4 + 2*i],     sv.x);                       \
                ull d1 = psub(BUF[r*4 + 2*i + 1], sv.y);                       \
                aL[r] = pfma(d0, d0, aL[r]);                                   \
                aL[r] = pfma(d1, d1, aL[r]);                                   \
                aS[r] = pfma(d0 & ABS2, wv.x, aS[r]);                          \
                aS[r] = pfma(d1 & ABS2, wv.y, aS[r]);                          \
            }                                                                  \
        }                                                                      \
    } while (0)

    LOADQ(qA, 0);
#pragma unroll 4
    for (int c = 0; c < 64; c += 2) {
        LOADQ(qB, c + 1);
        COMPUTE(qA, c);
        if (c + 2 < 64) LOADQ(qA, c + 2);
        COMPUTE(qB, c + 1);
    }

    // Finalize per-lane (support = lane) scores for the 4 rows.
    float sc[4], l2[4];
#pragma unroll
    for (int r = 0; r < 4; r++) {
        sc[r] = plo(aS[r]) + phi(aS[r]);
        l2[r] = __fsqrt_rn(plo(aL[r]) + phi(aL[r]));
        if (lane >= SN) { sc[r] = -3.4e38f; l2[r] = 0.0f; }
    }

    // Warp softmax over supports + weighted sums, 4 rows.
    float m[4];
#pragma unroll
    for (int r = 0; r < 4; r++) m[r] = sc[r];
#pragma unroll
    for (int d = 16; d; d >>= 1)
#pragma unroll
        for (int r = 0; r < 4; r++)
            m[r] = fmaxf(m[r], __shfl_xor_sync(0xffffffffu, m[r], d));

    float se[4], sd[4], sl[4];
#pragma unroll
    for (int r = 0; r < 4; r++) {
        float e = __expf(sc[r] - m[r]);
        se[r] = e; sd[r] = e * dyv; sl[r] = l2[r];
    }
#pragma unroll
    for (int d = 16; d; d >>= 1)
#pragma unroll
        for (int r = 0; r < 4; r++) {
            se[r] += __shfl_xor_sync(0xffffffffu, se[r], d);
            sd[r] += __shfl_xor_sync(0xffffffffu, sd[r], d);
            sl[r] += __shfl_xor_sync(0xffffffffu, sl[r], d);
        }

    if (lane == 0) {
        const int r0 = 4 * quad;
#pragma unroll
        for (int r = 0; r < 4; r++) {
            out[r0 + r]      = (sd[r] / se[r]) * scl + bia + qp[r0 + r];
            out[QN + r0 + r] = sl[r] * (1.0f / (float)SN);
        }
    }
}

extern "C" void kernel_launch(void* const* d_in, const int* in_sizes, int n_in,
                              void* d_out, int out_size) {
    const float* qenc   = (const float*)d_in[0];
    const float* senc   = (const float*)d_in[1];
    const float* sy     = (const float*)d_in[2];
    const float* sp     = (const float*)d_in[3];
    const float* qp     = (const float*)d_in[4];
    const float* w      = (const float*)d_in[5];
    // d_in[6] = fc1_b (softmax-invariant, unused)
    const float* ascale = (const float*)d_in[7];
    const float* abias  = (const float*)d_in[8];
    const int*   nsamp  = (const int*)d_in[9];

    float* out = (float*)d_out;

    const int smemBytes = (32 * STRIDE + DN) * (int)sizeof(float); // ~68 KB
    cudaFuncSetAttribute(resus_kernel,
                         cudaFuncAttributeMaxDynamicSharedMemorySize, smemBytes);

    resus_kernel<<<GRID, THREADS, smemBytes>>>(qenc, senc, sy, sp, qp, w,
                                               ascale, abias, nsamp, out);
}

// round 5
// speedup vs baseline: 1.6454x; 1.0735x over previous
#include <cuda_runtime.h>
#include <cstdint>

#define QN 8192
#define SN 30
#define DN 512

constexpr int THREADS    = 448;            // 14 warps = 7 pairs
constexpr int GRID       = 148;
constexpr int ROWS       = 8;              // q rows per tile
constexpr int NTILE      = QN / ROWS;      // 1024
constexpr int DHALF      = 256;            // d per warp (pair splits d)
constexpr int QCHUNK     = 64;             // floats per row per staged chunk
constexpr int NCHUNK     = DHALF / QCHUNK; // 4
constexpr int STRIDE     = 516;            // support smem stride: conflict-free
constexpr int PAIRS_BLK  = 7;

typedef unsigned long long ull;

__device__ __forceinline__ ull psub(ull a, ull b) {
    ull r; asm("sub.rn.f32x2 %0, %1, %2;" : "=l"(r) : "l"(a), "l"(b)); return r;
}
__device__ __forceinline__ ull pfma(ull a, ull b, ull c) {
    ull r; asm("fma.rn.f32x2 %0, %1, %2, %3;" : "=l"(r) : "l"(a), "l"(b), "l"(c)); return r;
}
__device__ __forceinline__ float plo(ull a) { return __uint_as_float((unsigned)(a & 0xffffffffu)); }
__device__ __forceinline__ float phi(ull a) { return __uint_as_float((unsigned)(a >> 32)); }
__device__ __forceinline__ void cpasync16(uint32_t dst, const float* src) {
    asm volatile("cp.async.ca.shared.global [%0], [%1], 16;" :: "r"(dst), "l"(src));
}

#define ABS2 0x7fffffff7fffffffULL

__global__ __launch_bounds__(THREADS, 1)
void resus_kernel(const float* __restrict__ qenc,
                  const float* __restrict__ senc,
                  const float* __restrict__ sy,
                  const float* __restrict__ sp,
                  const float* __restrict__ qp,
                  const float* __restrict__ w,
                  const float* __restrict__ ascale,
                  const float* __restrict__ abias,
                  const int*   __restrict__ nsamp,
                  float* __restrict__ out)
{
    extern __shared__ float sh[];
    float* sT  = sh;                       // [32][STRIDE] supports (30 real + 2 zero)
    float* wSh = sT + 32 * STRIDE;         // [512]
    float* qB  = wSh + DN;                 // [14 warps][2 bufs][ROWS][QCHUNK]
    float* cmb = qB + 14 * 2 * ROWS * QCHUNK; // [7 pairs][2 halves][ROWS][32] float2

    const int tid  = threadIdx.x;
    const int lane = tid & 31;
    const int warp = tid >> 5;

    for (int idx = tid; idx < 32 * DN; idx += THREADS) {
        int s = idx >> 9, d = idx & (DN - 1);
        sT[s * STRIDE + d] = (s < SN) ? senc[idx] : 0.0f;
    }
    for (int d = tid; d < DN; d += THREADS) wSh[d] = w[d];

    float dyv = 0.0f;
    if (lane < SN) dyv = sy[lane] - 1.0f / (1.0f + __expf(-sp[lane]));
    const int ia = nsamp[0] - 1;
    const float scl = fabsf(ascale[ia]);
    const float bia = abias[ia];
    __syncthreads();

    const int pairIB = warp >> 1;     // 0..6
    const int half   = warp & 1;      // which d-half this warp owns
    const int tile   = blockIdx.x * PAIRS_BLK + pairIB;
    if (tile >= NTILE) return;

    const float* qbase = qenc + (size_t)tile * ROWS * DN + half * DHALF;
    float* qw = qB + warp * (2 * ROWS * QCHUNK);
    const uint32_t qwS = (uint32_t)__cvta_generic_to_shared(qw);
    const float* sRow = sT + lane * STRIDE + half * DHALF;
    const float* wRow = wSh + half * DHALF;

    ull aS[ROWS], aL[ROWS];
#pragma unroll
    for (int r = 0; r < ROWS; r++) { aS[r] = 0; aL[r] = 0; }

    // Stage one 8-row x 64-float chunk via cp.async (4 x 512B per warp).
    auto stageChunk = [&](int c, int b) {
        const int rowA = lane >> 4;            // 0..1
        const int col  = (lane & 15) * 4;      // 16B per lane
#pragma unroll
        for (int i = 0; i < 4; i++) {
            int r = 2 * i + rowA;
            const float* src = qbase + (size_t)r * DN + c * QCHUNK + col;
            uint32_t dst = qwS + (uint32_t)((b * ROWS * QCHUNK + r * QCHUNK + col) * 4);
            cpasync16(dst, src);
        }
        asm volatile("cp.async.commit_group;" ::: "memory");
    };

    auto computeChunk = [&](int c, int b) {
        const float* qbuf = qw + b * ROWS * QCHUNK;
#pragma unroll 4
        for (int t = 0; t < QCHUNK / 4; t++) {
            const int dd = c * QCHUNK + t * 4;
            ulonglong2 sv = *reinterpret_cast<const ulonglong2*>(sRow + dd);
            ulonglong2 wv = *reinterpret_cast<const ulonglong2*>(wRow + dd);
#pragma unroll
            for (int r = 0; r < ROWS; r++) {
                ulonglong2 qv = *reinterpret_cast<const ulonglong2*>(qbuf + r * QCHUNK + t * 4);
                ull d0 = psub(qv.x, sv.x);
                ull d1 = psub(qv.y, sv.y);
                aL[r] = pfma(d0, d0, aL[r]);
                aL[r] = pfma(d1, d1, aL[r]);
                aS[r] = pfma(d0 & ABS2, wv.x, aS[r]);
                aS[r] = pfma(d1 & ABS2, wv.y, aS[r]);
            }
        }
    };

    stageChunk(0, 0);
#pragma unroll
    for (int c = 0; c < NCHUNK; c++) {
        if (c + 1 < NCHUNK) {
            stageChunk(c + 1, (c + 1) & 1);
            asm volatile("cp.async.wait_group 1;" ::: "memory");
        } else {
            asm volatile("cp.async.wait_group 0;" ::: "memory");
        }
        __syncwarp();
        computeChunk(c, c & 1);
    }

    // ---- Pair combine: partials per (row, lane=support), sqrt AFTER combining ----
    float2* cp2 = reinterpret_cast<float2*>(cmb) + pairIB * (2 * ROWS * 32);
#pragma unroll
    for (int r = 0; r < ROWS; r++) {
        float scP  = plo(aS[r]) + phi(aS[r]);
        float ssqP = plo(aL[r]) + phi(aL[r]);
        cp2[(half * ROWS + r) * 32 + lane] = make_float2(scP, ssqP);
    }
    asm volatile("bar.sync %0, 64;" :: "r"(1 + pairIB) : "memory");

    // Each warp of the pair finishes 4 rows.
#pragma unroll
    for (int k = 0; k < 4; k++) {
        const int r = half * 4 + k;
        float2 pa = cp2[(0 * ROWS + r) * 32 + lane];
        float2 pb = cp2[(1 * ROWS + r) * 32 + lane];
        float sc  = pa.x + pb.x;
        float l2v = __fsqrt_rn(pa.y + pb.y);
        if (lane >= SN) { sc = -3.4e38f; l2v = 0.0f; }

        float m = sc;
#pragma unroll
        for (int d = 16; d; d >>= 1) m = fmaxf(m, __shfl_xor_sync(0xffffffffu, m, d));
        float e  = __expf(sc - m);
        float se = e, sd = e * dyv, sl = l2v;
#pragma unroll
        for (int d = 16; d; d >>= 1) {
            se += __shfl_xor_sync(0xffffffffu, se, d);
            sd += __shfl_xor_sync(0xffffffffu, sd, d);
            sl += __shfl_xor_sync(0xffffffffu, sl, d);
        }
        if (lane == 0) {
            const int row = tile * ROWS + r;
            out[row]      = (sd / se) * scl + bia + qp[row];
            out[QN + row] = sl * (1.0f / (float)SN);
        }
    }
}

extern "C" void kernel_launch(void* const* d_in, const int* in_sizes, int n_in,
                              void* d_out, int out_size) {
    const float* qenc   = (const float*)d_in[0];
    const float* senc   = (const float*)d_in[1];
    const float* sy     = (const float*)d_in[2];
    const float* sp     = (const float*)d_in[3];
    const float* qp     = (const float*)d_in[4];
    const float* w      = (const float*)d_in[5];
    // d_in[6] = fc1_b (softmax-invariant, unused)
    const float* ascale = (const float*)d_in[7];
    const float* abias  = (const float*)d_in[8];
    const int*   nsamp  = (const int*)d_in[9];

    float* out = (float*)d_out;

    // smem: supports 32*516 + w 512 + qBuf 14*2*8*64 + combine 7*2*8*32*2 floats
    const int smemFloats = 32 * STRIDE + DN + 14 * 2 * ROWS * QCHUNK + PAIRS_BLK * 2 * ROWS * 32 * 2;
    const int smemBytes = smemFloats * (int)sizeof(float); // ~150 KB
    cudaFuncSetAttribute(resus_kernel,
                         cudaFuncAttributeMaxDynamicSharedMemorySize, smemBytes);

    resus_kernel<<<GRID, THREADS, smemBytes>>>(qenc, senc, sy, sp, qp, w,
                                               ascale, abias, nsamp, out);
}

// round 6
// speedup vs baseline: 1.7698x; 1.0756x over previous
#include <cuda_runtime.h>
#include <cstdint>

#define QN 8192
#define SN 30
#define DN 512

constexpr int THREADS   = 896;             // 28 warps = 14 pairs
constexpr int GRID      = 148;
constexpr int ROWS      = 4;               // q rows per tile
constexpr int NTILE     = QN / ROWS;       // 2048
constexpr int DHALF     = 256;             // d per warp (pair splits d)
constexpr int QCHUNK    = 64;              // floats per row per staged chunk
constexpr int NCHUNK    = DHALF / QCHUNK;  // 4
constexpr int STRIDE    = 516;             // support smem stride: conflict-free
constexpr int PAIRS_BLK = 14;

typedef unsigned long long ull;

__device__ __forceinline__ ull psub(ull a, ull b) {
    ull r; asm("sub.rn.f32x2 %0, %1, %2;" : "=l"(r) : "l"(a), "l"(b)); return r;
}
__device__ __forceinline__ ull pfma(ull a, ull b, ull c) {
    ull r; asm("fma.rn.f32x2 %0, %1, %2, %3;" : "=l"(r) : "l"(a), "l"(b), "l"(c)); return r;
}
__device__ __forceinline__ float plo(ull a) { return __uint_as_float((unsigned)(a & 0xffffffffu)); }
__device__ __forceinline__ float phi(ull a) { return __uint_as_float((unsigned)(a >> 32)); }
__device__ __forceinline__ void cpasync16(uint32_t dst, const float* src) {
    asm volatile("cp.async.ca.shared.global [%0], [%1], 16;" :: "r"(dst), "l"(src));
}

#define ABS2 0x7fffffff7fffffffULL

__global__ __launch_bounds__(THREADS, 1)
void resus_kernel(const float* __restrict__ qenc,
                  const float* __restrict__ senc,
                  const float* __restrict__ sy,
                  const float* __restrict__ sp,
                  const float* __restrict__ qp,
                  const float* __restrict__ w,
                  const float* __restrict__ ascale,
                  const float* __restrict__ abias,
                  const int*   __restrict__ nsamp,
                  float* __restrict__ out)
{
    extern __shared__ float sh[];
    float* sT  = sh;                         // [32][STRIDE] supports (30 real + 2 zero)
    float* wSh = sT + 32 * STRIDE;           // [512]
    float* qB  = wSh + DN;                   // [28 warps][2 bufs][ROWS][QCHUNK]
    float* cmb = qB + 28 * 2 * ROWS * QCHUNK; // [14 pairs][2 halves][ROWS][32] float2

    const int tid  = threadIdx.x;
    const int lane = tid & 31;
    const int warp = tid >> 5;

    for (int idx = tid; idx < 32 * DN; idx += THREADS) {
        int s = idx >> 9, d = idx & (DN - 1);
        sT[s * STRIDE + d] = (s < SN) ? senc[idx] : 0.0f;
    }
    for (int d = tid; d < DN; d += THREADS) wSh[d] = w[d];

    float dyv = 0.0f;
    if (lane < SN) dyv = sy[lane] - 1.0f / (1.0f + __expf(-sp[lane]));
    const int ia = nsamp[0] - 1;
    const float scl = fabsf(ascale[ia]);
    const float bia = abias[ia];
    __syncthreads();

    const int pairIB = warp & 13 ? warp % 14 : warp % 14; // warp % 14
    const int half   = warp / 14;                         // 0 or 1
    const int tile   = blockIdx.x * PAIRS_BLK + (warp % 14);
    if (tile >= NTILE) return;

    const float* qbase = qenc + (size_t)tile * ROWS * DN + half * DHALF;
    float* qw = qB + warp * (2 * ROWS * QCHUNK);
    const uint32_t qwS = (uint32_t)__cvta_generic_to_shared(qw);
    const float* sRow = sT + lane * STRIDE + half * DHALF;
    const float* wRow = wSh + half * DHALF;

    ull aS[ROWS], aL[ROWS];
#pragma unroll
    for (int r = 0; r < ROWS; r++) { aS[r] = 0; aL[r] = 0; }

    // Stage one 4-row x 64-float chunk via cp.async (2 x 16B per lane).
    auto stageChunk = [&](int c, int b) {
#pragma unroll
        for (int i = 0; i < 2; i++) {
            int seg = lane + 32 * i;          // 0..63
            int r   = seg >> 4;               // 0..3
            int col = (seg & 15) * 4;         // 0..60
            const float* src = qbase + (size_t)r * DN + c * QCHUNK + col;
            uint32_t dst = qwS + (uint32_t)((b * ROWS * QCHUNK + r * QCHUNK + col) * 4);
            cpasync16(dst, src);
        }
        asm volatile("cp.async.commit_group;" ::: "memory");
    };

    auto computeChunk = [&](int c, int b) {
        const float* qbuf = qw + b * ROWS * QCHUNK;
#pragma unroll 4
        for (int t = 0; t < QCHUNK / 4; t++) {
            const int dd = c * QCHUNK + t * 4;
            ulonglong2 sv = *reinterpret_cast<const ulonglong2*>(sRow + dd);
            ulonglong2 wv = *reinterpret_cast<const ulonglong2*>(wRow + dd);
#pragma unroll
            for (int r = 0; r < ROWS; r++) {
                ulonglong2 qv = *reinterpret_cast<const ulonglong2*>(qbuf + r * QCHUNK + t * 4);
                ull d0 = psub(qv.x, sv.x);
                ull d1 = psub(qv.y, sv.y);
                aL[r] = pfma(d0, d0, aL[r]);
                aL[r] = pfma(d1, d1, aL[r]);
                aS[r] = pfma(d0 & ABS2, wv.x, aS[r]);
                aS[r] = pfma(d1 & ABS2, wv.y, aS[r]);
            }
        }
    };

    stageChunk(0, 0);
#pragma unroll
    for (int c = 0; c < NCHUNK; c++) {
        if (c + 1 < NCHUNK) {
            stageChunk(c + 1, (c + 1) & 1);
            asm volatile("cp.async.wait_group 1;" ::: "memory");
        } else {
            asm volatile("cp.async.wait_group 0;" ::: "memory");
        }
        __syncwarp();
        computeChunk(c, c & 1);
    }

    // ---- Pair combine: partials per (row, lane=support), sqrt AFTER combining ----
    float2* cp2 = reinterpret_cast<float2*>(cmb) + (warp % 14) * (2 * ROWS * 32);
#pragma unroll
    for (int r = 0; r < ROWS; r++) {
        float scP  = plo(aS[r]) + phi(aS[r]);
        float ssqP = plo(aL[r]) + phi(aL[r]);
        cp2[(half * ROWS + r) * 32 + lane] = make_float2(scP, ssqP);
    }
    asm volatile("bar.sync %0, 64;" :: "r"(1 + (warp % 14)) : "memory");

    // Each warp of the pair finishes 2 rows.
#pragma unroll
    for (int k = 0; k < 2; k++) {
        const int r = half * 2 + k;
        float2 pa = cp2[(0 * ROWS + r) * 32 + lane];
        float2 pb = cp2[(1 * ROWS + r) * 32 + lane];
        float sc  = pa.x + pb.x;
        float l2v = __fsqrt_rn(pa.y + pb.y);
        if (lane >= SN) { sc = -3.4e38f; l2v = 0.0f; }

        float m = sc;
#pragma unroll
        for (int d = 16; d; d >>= 1) m = fmaxf(m, __shfl_xor_sync(0xffffffffu, m, d));
        float e  = __expf(sc - m);
        float se = e, sd = e * dyv, sl = l2v;
#pragma unroll
        for (int d = 16; d; d >>= 1) {
            se += __shfl_xor_sync(0xffffffffu, se, d);
            sd += __shfl_xor_sync(0xffffffffu, sd, d);
            sl += __shfl_xor_sync(0xffffffffu, sl, d);
        }
        if (lane == 0) {
            const int row = tile * ROWS + r;
            out[row]      = (sd / se) * scl + bia + qp[row];
            out[QN + row] = sl * (1.0f / (float)SN);
        }
    }
}

extern "C" void kernel_launch(void* const* d_in, const int* in_sizes, int n_in,
                              void* d_out, int out_size) {
    const float* qenc   = (const float*)d_in[0];
    const float* senc   = (const float*)d_in[1];
    const float* sy     = (const float*)d_in[2];
    const float* sp     = (const float*)d_in[3];
    const float* qp     = (const float*)d_in[4];
    const float* w      = (const float*)d_in[5];
    // d_in[6] = fc1_b (softmax-invariant, unused)
    const float* ascale = (const float*)d_in[7];
    const float* abias  = (const float*)d_in[8];
    const int*   nsamp  = (const int*)d_in[9];

    float* out = (float*)d_out;

    // smem floats: supports 32*516 + w 512 + qBuf 28*2*4*64 + combine 14*2*4*32*2
    const int smemFloats = 32 * STRIDE + DN + 28 * 2 * ROWS * QCHUNK + PAIRS_BLK * 2 * ROWS * 32 * 2;
    const int smemBytes = smemFloats * (int)sizeof(float); // ~154 KB
    cudaFuncSetAttribute(resus_kernel,
                         cudaFuncAttributeMaxDynamicSharedMemorySize, smemBytes);

    resus_kernel<<<GRID, THREADS, smemBytes>>>(qenc, senc, sy, sp, qp, w,
                                               ascale, abias, nsamp, out);
}